// round 17
// baseline (speedup 1.0000x reference)
#include <cuda_runtime.h>
#include <cuda_fp16.h>
#include <cstdint>

#define N_  2
#define C_  128
#define D_  32
#define H_  64
#define W_  64
#define R_  256
#define PD  4
#define PH  7
#define PW  7
#define HW_ (H_ * W_)
#define DHW (D_ * H_ * W_)
#define NCELL (PH * PW)           // 49
#define TAPCAP 68                 // 64 + pad to x4

// 64 MB static scratch: NDHWC features quantized to fp16
__device__ __half g_feat_t[(size_t)N_ * DHW * C_];

// ---------------------------------------------------------------------------
// Transpose NCDHW fp32 -> NDHWC fp16 for ONE batch (64x64 tiles, float2 ldcs)
// ---------------------------------------------------------------------------
__global__ void __launch_bounds__(256) transpose_ndhwc_h(const float* __restrict__ in,
                                                         __half* __restrict__ out,
                                                         int n) {
    __shared__ __half tile[64][66];
    const int s0 = blockIdx.x * 64;
    const int c0 = blockIdx.y * 64;
    const int tx = threadIdx.x, ty = threadIdx.y;

    const float* ip = in  + (size_t)n * C_ * DHW;
    __half*      op = out + (size_t)n * DHW * C_;

#pragma unroll
    for (int i = 0; i < 64; i += 8) {
        const float2 v = __ldcs(reinterpret_cast<const float2*>(
            &ip[(size_t)(c0 + ty + i) * DHW + s0 + 2 * tx]));
        tile[2 * tx][ty + i]     = __float2half(v.x);
        tile[2 * tx + 1][ty + i] = __float2half(v.y);
    }
    __syncthreads();

#pragma unroll
    for (int i = 0; i < 64; i += 8) {
        const int s = ty + i;
        __half2 v = *reinterpret_cast<const __half2*>(&tile[s][tx * 2]);
        *reinterpret_cast<__half2*>(&op[(size_t)(s0 + s) * C_ + c0 + tx * 2]) = v;
    }
}

// ---------------------------------------------------------------------------
// Per-axis separable taps
// ---------------------------------------------------------------------------
__device__ __forceinline__ void axis_taps(float c0, float c1, int size,
                                          int& base, float w[4]) {
    w[0] = w[1] = w[2] = w[3] = 0.0f;
    const float szf = (float)size;

    const bool v0 = (c0 >= -1.0f) && (c0 <= szf);
    float cc0 = fminf(fmaxf(c0, 0.0f), szf - 1.0f);
    const int lo0 = (int)floorf(cc0);
    const int hi0 = min(lo0 + 1, size - 1);
    const float f0 = cc0 - (float)lo0;

    const bool v1 = (c1 >= -1.0f) && (c1 <= szf);
    float cc1 = fminf(fmaxf(c1, 0.0f), szf - 1.0f);
    const int lo1 = (int)floorf(cc1);
    const int hi1 = min(lo1 + 1, size - 1);
    const float f1 = cc1 - (float)lo1;

    base = lo0;
    if (v0) { w[0]         += 1.0f - f0; w[hi0 - lo0] += f0; }
    if (v1) { w[lo1 - lo0] += 1.0f - f1; w[hi1 - lo0] += f1; }
}

__device__ __forceinline__ float sel4(int i, float a, float b, float c, float d) {
    return (i == 0) ? a : ((i == 1) ? b : ((i == 2) ? c : d));
}

__device__ __forceinline__ __half2 h2_from_bits(int b) {
    __half2 h;
    *reinterpret_cast<int*>(&h) = b;
    return h;
}

// ---------------------------------------------------------------------------
// Gather for rois of ONE batch (bfilter). Other-batch blocks exit early
// (warp-uniform). R15 loop: 4-tap fp16 chain, single fp32 flush per iter.
// ---------------------------------------------------------------------------
__global__ void __launch_bounds__(32 * PD, 12) roi3d_gather(const float* __restrict__ rois,
                                                            const uint2* __restrict__ fp,
                                                            float* __restrict__ out,
                                                            int bfilter) {
    __shared__ int2 taps[PD][TAPCAP];

    const int r    = blockIdx.x;
    const int cell = blockIdx.y;
    const int ph   = cell / PW;
    const int pw   = cell - ph * PW;
    const int pd   = threadIdx.y;          // warp id = pd
    const int lane = threadIdx.x;

    const float* roi = rois + r * 7;
    const int b = (int)__ldg(roi);
    if (b != bfilter) return;              // handled by the other launch

    const float x1 = __ldg(roi + 1) * 0.25f, y1 = __ldg(roi + 2) * 0.25f;
    const float z1 = __ldg(roi + 3) * 0.25f;
    const float x2 = __ldg(roi + 4) * 0.25f, y2 = __ldg(roi + 5) * 0.25f;
    const float z2 = __ldg(roi + 6) * 0.25f;
    const float sz = fmaxf(z2 - z1, 1.0f) * (1.0f / (PD * 2));
    const float sy = fmaxf(y2 - y1, 1.0f) * (1.0f / (PH * 2));
    const float sx = fmaxf(x2 - x1, 1.0f) * (1.0f / (PW * 2));
    const int bbase = b * DHW;

    const float zc0 = z1 + ((float)(pd * 2) + 0.5f) * sz;
    const float yc0 = y1 + ((float)(ph * 2) + 0.5f) * sy;
    const float xc0 = x1 + ((float)(pw * 2) + 0.5f) * sx;

    int bz, by, bx;
    float wz[4], wy[4], wx[4];
    axis_taps(zc0, zc0 + sz, D_, bz, wz);
    axis_taps(yc0, yc0 + sy, H_, by, wy);
    axis_taps(xc0, xc0 + sx, W_, bx, wx);
    wz[0] *= 0.125f; wz[1] *= 0.125f; wz[2] *= 0.125f; wz[3] *= 0.125f;

    // lane's combo decomposition: combo = zi*16 + yi*4 + xi; lane -> {lane, lane+32}
    const int zi0 = lane >> 4;             // 0..1 (combo B: zi0 + 2)
    const int yi0 = (lane >> 2) & 3;
    const int xi  = lane & 3;

    // direct IMAD offsets (uint2 units: voxel * 32)
    const int HW32 = HW_ * 32;
    const int W32  = W_ * 32;
    const int o0 = (bbase + bz * HW_) * 32 + zi0 * HW32 + (by + yi0) * W32
                 + (bx + xi) * 32;
    const int o1 = o0 + 2 * HW32;

    int2* wlist = taps[pd];

    // ---- cooperative compaction (weights packed as duplicated half2) ----
    int nt = 0;
    {
        const float wyx = sel4(yi0, wy[0], wy[1], wy[2], wy[3]) * wx[xi];

        const float w0 = (zi0 == 0 ? wz[0] : wz[1]) * wyx;
        unsigned bal = __ballot_sync(0xffffffffu, w0 != 0.0f);
        if (w0 != 0.0f) {
            int slot = __popc(bal & ((1u << lane) - 1u));
            __half2 wh = __float2half2_rn(w0);
            wlist[slot] = make_int2(o0, *reinterpret_cast<int*>(&wh));
        }
        nt = __popc(bal);

        const float w1 = (zi0 == 0 ? wz[2] : wz[3]) * wyx;
        unsigned bal1 = __ballot_sync(0xffffffffu, w1 != 0.0f);
        if (w1 != 0.0f) {
            int slot = nt + __popc(bal1 & ((1u << lane) - 1u));
            __half2 wh = __float2half2_rn(w1);
            wlist[slot] = make_int2(o1, *reinterpret_cast<int*>(&wh));
        }
        nt += __popc(bal1);
    }
    if (lane < 3) wlist[nt + lane] = make_int2(0, 0);   // zero-weight pad
    const int nt4 = (nt + 3) & ~3;
    __syncwarp();

    // ---- branch-free gather: 4-tap fp16 chain, one fp32 flush per iter ----
    const uint2* __restrict__ fpl = fp + lane;
    float4 acc = make_float4(0.0f, 0.0f, 0.0f, 0.0f);

    for (int j = 0; j < nt4; j += 4) {
        const int4 p0 = *reinterpret_cast<const int4*>(&wlist[j]);     // taps 0,1
        const int4 p1 = *reinterpret_cast<const int4*>(&wlist[j + 2]); // taps 2,3
        const uint2 v0 = __ldg(fpl + p0.x);
        const uint2 v1 = __ldg(fpl + p0.z);
        const uint2 v2 = __ldg(fpl + p1.x);
        const uint2 v3 = __ldg(fpl + p1.z);

        const __half2 w0 = h2_from_bits(p0.y);
        const __half2 w1 = h2_from_bits(p0.w);
        const __half2 w2 = h2_from_bits(p1.y);
        const __half2 w3 = h2_from_bits(p1.w);

        __half2 h01 = __hmul2(h2_from_bits((int)v0.x), w0);
        __half2 h23 = __hmul2(h2_from_bits((int)v0.y), w0);
        h01 = __hfma2(h2_from_bits((int)v1.x), w1, h01);
        h23 = __hfma2(h2_from_bits((int)v1.y), w1, h23);
        h01 = __hfma2(h2_from_bits((int)v2.x), w2, h01);
        h23 = __hfma2(h2_from_bits((int)v2.y), w2, h23);
        h01 = __hfma2(h2_from_bits((int)v3.x), w3, h01);
        h23 = __hfma2(h2_from_bits((int)v3.y), w3, h23);

        float2 f;
        f = __half22float2(h01); acc.x += f.x; acc.y += f.y;
        f = __half22float2(h23); acc.z += f.x; acc.w += f.y;
    }

    // ---- direct stores: out[r][c][pd][ph][pw], c = lane*4 ----
    const int ob = ((r * C_ + lane * 4) * PD + pd) * NCELL + cell;
    out[ob]                  = acc.x;
    out[ob + PD * NCELL]     = acc.y;
    out[ob + 2 * PD * NCELL] = acc.z;
    out[ob + 3 * PD * NCELL] = acc.w;
}

// ---------------------------------------------------------------------------
// Launch: fork-join pipeline.
//   s0: T(0) -> e0 -> T(1) -> gather(b=1) -> wait eG
//   s2:          wait e0 -> gather(b=0) -> eG
// gather(b) depends only on T(b); the two gathers write disjoint outputs.
// ---------------------------------------------------------------------------
extern "C" void kernel_launch(void* const* d_in, const int* in_sizes, int n_in,
                              void* d_out, int out_size) {
    const float* features = (const float*)d_in[0];
    const float* rois     = (const float*)d_in[1];
    float*       out      = (float*)d_out;

    __half* feat_t = nullptr;
    cudaGetSymbolAddress((void**)&feat_t, g_feat_t);

    static cudaStream_t s2 = nullptr;
    static cudaEvent_t  e0 = nullptr, eG = nullptr;
    if (s2 == nullptr) {   // first call is the uncaptured correctness run
        cudaStreamCreateWithFlags(&s2, cudaStreamNonBlocking);
        cudaEventCreateWithFlags(&e0, cudaEventDisableTiming);
        cudaEventCreateWithFlags(&eG, cudaEventDisableTiming);
    }

    dim3 tg(DHW / 64, C_ / 64, 1);
    dim3 tb(32, 8);
    dim3 rg(R_, NCELL);
    dim3 rb(32, PD);

    // T(0) on main stream
    transpose_ndhwc_h<<<tg, tb>>>(features, feat_t, 0);
    cudaEventRecord(e0, 0);

    // gather(b=0) on s2, after T(0)
    cudaStreamWaitEvent(s2, e0, 0);
    roi3d_gather<<<rg, rb, 0, s2>>>(rois, (const uint2*)feat_t, out, 0);
    cudaEventRecord(eG, s2);

    // T(1) then gather(b=1) on main stream (overlaps gather b=0)
    transpose_ndhwc_h<<<tg, tb>>>(features, feat_t, 1);
    roi3d_gather<<<rg, rb>>>(rois, (const uint2*)feat_t, out, 1);

    // join
    cudaStreamWaitEvent(0, eG, 0);
}